// round 4
// baseline (speedup 1.0000x reference)
#include <cuda_runtime.h>
#include <cstdint>

typedef unsigned long long u64;

#define HWDIM 224
#define HWPIX (HWDIM*HWDIM)   // 50176
#define NB    16
#define NTOK  49
#define CH    64
#define NOUT  80               // q(8) k(8) v(64)

// scratch: window-gathered qkv [b][l][t][80]
__device__ float g_qkv[(size_t)NB * 1024 * NTOK * NOUT];

__device__ __forceinline__ u64 f2swap(u64 v){
    u64 r;
    asm("{\n\t.reg .b32 l,h;\n\tmov.b64 {l,h}, %1;\n\tmov.b64 %0, {h,l};\n\t}"
        : "=l"(r) : "l"(v));
    return r;
}
__device__ __forceinline__ void ffma2(u64 &d, u64 a, u64 b){
    asm("fma.rn.f32x2 %0, %1, %2, %0;" : "+l"(d) : "l"(a), "l"(b));
}
__device__ __forceinline__ float f2lo(u64 v){ return __int_as_float((unsigned)(v & 0xffffffffull)); }
__device__ __forceinline__ float f2hi(u64 v){ return __int_as_float((unsigned)(v >> 32)); }

// ===================== K1: fused QKV projection =====================
// block = 128 threads, 128 pixels. tile = 8 pixels x 10 outs (diag f32x2).
// smem: xs[64][128] @0 (8192) | wct[64][80] @8192 (5120) | bias @13312 (80)
#define K1_SMEM_FLOATS 13392
#define K1_SMEM_BYTES  (K1_SMEM_FLOATS*4)

__global__ void __launch_bounds__(128, 4)
proj_kernel(const float* __restrict__ x,
            const float* __restrict__ Wq, const float* __restrict__ bq,
            const float* __restrict__ Wk, const float* __restrict__ bk,
            const float* __restrict__ Wv, const float* __restrict__ bv)
{
    extern __shared__ float s1[];
    const int tid = threadIdx.x;
    const int blk = blockIdx.x;               // 16 * 392
    const int b   = blk / 392;
    const int hw0 = (blk - b * 392) * 128;

    // stage raw weights [o][c] stride 65 into xs area (overwritten later)
    for (int idx = tid; idx < 512; idx += 128) {
        int o = idx >> 6, c = idx & 63;
        s1[o * 65 + c]       = __ldg(&Wq[idx]);
        s1[520 + o * 65 + c] = __ldg(&Wk[idx]);
    }
    for (int idx = tid; idx < 4096; idx += 128) {
        int o = idx >> 6, c = idx & 63;
        s1[1040 + o * 65 + c] = __ldg(&Wv[idx]);
    }
    if (tid < 80)
        s1[13312 + tid] = (tid < 8) ? __ldg(&bq[tid])
                        : (tid < 16) ? __ldg(&bk[tid - 8])
                                     : __ldg(&bv[tid - 16]);
    __syncthreads();
    // transpose -> wct[c][80]: q(0..7) k(8..15) v(16..79)
    for (int idx = tid; idx < 5120; idx += 128) {
        int c = idx / 80, o = idx - c * 80;
        float v = (o < 8)  ? s1[o * 65 + c]
                : (o < 16) ? s1[520 + (o - 8) * 65 + c]
                           : s1[1040 + (o - 16) * 65 + c];
        s1[8192 + c * 80 + o] = v;
    }
    __syncthreads();
    // load x tile -> xs[c][p] (overwrites raw stage)
    const float* xb = x + (size_t)b * CH * HWPIX + hw0;
    for (int idx = tid; idx < 8192; idx += 128) {
        int c = idx >> 7, p = idx & 127;
        s1[c * 128 + p] = __ldg(&xb[(size_t)c * HWPIX + p]);
    }
    __syncthreads();

    // compute: tile 8 px x 10 outs
    const int og = tid & 7, pg = tid >> 3;
    const int o0 = og * 10, p0 = pg * 8;

    u64 accA[4][5], accB[4][5];
    #pragma unroll
    for (int p = 0; p < 4; p++)
        #pragma unroll
        for (int q = 0; q < 5; q++) { accA[p][q] = 0ull; accB[p][q] = 0ull; }

    const u64* xbase = reinterpret_cast<const u64*>(s1) + (p0 >> 1);
    const u64* wbase = reinterpret_cast<const u64*>(s1 + 8192) + og * 5;

    #pragma unroll 2
    for (int c = 0; c < CH; c++) {
        u64 xv[4];
        #pragma unroll
        for (int p = 0; p < 4; p++) xv[p] = xbase[c * 64 + p];
        #pragma unroll
        for (int q = 0; q < 5; q++) {
            u64 wn = wbase[c * 40 + q];
            u64 ws = f2swap(wn);
            #pragma unroll
            for (int p = 0; p < 4; p++) {
                ffma2(accA[p][q], xv[p], wn);
                ffma2(accB[p][q], xv[p], ws);
            }
        }
    }

    const float* sb = s1 + 13312;
    #pragma unroll
    for (int p = 0; p < 4; p++) {
        float oa[10], oc[10];
        #pragma unroll
        for (int q = 0; q < 5; q++) {
            oa[2*q]   = f2lo(accA[p][q]) + sb[o0 + 2*q];
            oa[2*q+1] = f2lo(accB[p][q]) + sb[o0 + 2*q + 1];
            oc[2*q]   = f2hi(accB[p][q]) + sb[o0 + 2*q];
            oc[2*q+1] = f2hi(accA[p][q]) + sb[o0 + 2*q + 1];
        }
        // two pixels: ta = p0+2p, tb = ta+1 (within 128-px chunk)
        #pragma unroll
        for (int e = 0; e < 2; e++) {
            int hw = hw0 + p0 + 2 * p + e;
            int h  = hw / HWDIM, w = hw - h * HWDIM;
            int l  = (h / 7) * 32 + (w / 7);
            int t  = (h % 7) * 7 + (w % 7);
            size_t row = ((((size_t)b << 10) + l) * NTOK + t) * NOUT + o0;
            float2* dst = reinterpret_cast<float2*>(g_qkv + row);
            const float* src = e ? oc : oa;
            #pragma unroll
            for (int q = 0; q < 5; q++)
                dst[q] = make_float2(src[2*q], src[2*q+1]);
        }
    }
}

// ===================== K2: windowed attention =====================
// block = 256 threads, 4 horizontally-adjacent windows.
// per-window pool (6680 floats): qs[49*8]@0(400) ks@400(400) att[49][56]@800(2744,->3544) vs[49][64]@3544(3136)
// OS[49][66] (3234) overlays @0 after AV.
#define PW 6680
#define K2_SMEM_FLOATS (4*PW)          // 26720
#define K2_SMEM_BYTES  (K2_SMEM_FLOATS*4)

__global__ void __launch_bounds__(256, 2)
attn_kernel(const float* __restrict__ x,
            const float* __restrict__ gamma,
            float* __restrict__ out)
{
    extern __shared__ float s2[];
    const int tid = threadIdx.x;
    const int blk = blockIdx.x;       // 16 b * 32 wh * 8 wq
    const int b   = blk >> 8;
    const int rem = blk & 255;
    const int wh  = rem >> 3;
    const int wq  = rem & 7;

    // ---- stage q,k,v (15680 contiguous floats from g_qkv) ----
    const size_t qbase = (((size_t)b << 10) + wh * 32 + wq * 4) * (NTOK * NOUT);
    for (int idx = tid; idx < 4 * NTOK * NOUT; idx += 256) {
        float v   = g_qkv[qbase + idx];
        int win   = idx / (NTOK * NOUT);
        int r     = idx - win * (NTOK * NOUT);
        int t     = r / NOUT;
        int col   = r - t * NOUT;
        float* pool = s2 + win * PW;
        if (col < 8)       pool[t * 8 + col] = v;
        else if (col < 16) pool[400 + t * 8 + (col - 8)] = v;
        else               pool[3544 + t * 64 + (col - 16)] = v;
    }
    // zero att pad columns n = 49..55
    for (int idx = tid; idx < 4 * 49 * 7; idx += 256) {
        int win = idx / 343;
        int r   = idx - win * 343;
        int m   = r / 7, j = r - m * 7;
        s2[win * PW + 800 + m * 56 + 49 + j] = 0.0f;
    }
    __syncthreads();

    // ---- logits: attT[m][n] = <q_n, k_m>, 7x7 tiles, 196 threads ----
    if (tid < 196) {
        int win = tid / 49;
        int r   = tid - win * 49;
        int n0  = (r / 7) * 7, m0 = (r % 7) * 7;
        const float* qp = s2 + win * PW;
        const float* kp = qp + 400;
        float acc[7][7];
        #pragma unroll
        for (int i = 0; i < 7; i++)
            #pragma unroll
            for (int j = 0; j < 7; j++) acc[i][j] = 0.0f;
        #pragma unroll
        for (int c = 0; c < 8; c++) {
            float qv[7], kv[7];
            #pragma unroll
            for (int i = 0; i < 7; i++) qv[i] = qp[(n0 + i) * 8 + c];
            #pragma unroll
            for (int j = 0; j < 7; j++) kv[j] = kp[(m0 + j) * 8 + c];
            #pragma unroll
            for (int i = 0; i < 7; i++)
                #pragma unroll
                for (int j = 0; j < 7; j++) acc[i][j] = fmaf(qv[i], kv[j], acc[i][j]);
        }
        float* atp = s2 + win * PW + 800;
        #pragma unroll
        for (int i = 0; i < 7; i++)
            #pragma unroll
            for (int j = 0; j < 7; j++)
                atp[(m0 + j) * 56 + (n0 + i)] = acc[i][j];
    }
    __syncthreads();

    // ---- softmax over m (columns of attT), 196 threads ----
    if (tid < 196) {
        int win = tid / 49;
        int n   = tid - win * 49;
        float* atp = s2 + win * PW + 800 + n;
        float mx = atp[0];
        #pragma unroll 7
        for (int m = 1; m < NTOK; m++) mx = fmaxf(mx, atp[m * 56]);
        float s = 0.0f;
        #pragma unroll 7
        for (int m = 0; m < NTOK; m++) {
            float e = __expf(atp[m * 56] - mx);
            atp[m * 56] = e;
            s += e;
        }
        float rinv = 1.0f / s;
        #pragma unroll 7
        for (int m = 0; m < NTOK; m++) atp[m * 56] *= rinv;
    }
    __syncthreads();

    // ---- AV: out[n][c] = sum_m att[m][n] * v[m][c], tile 8t x 8c, 224 threads ----
    u64 accA[4][4], accB[4][4];
    int a_win = 0, a_t0 = 0, a_c0 = 0;
    if (tid < 224) {
        a_win = tid / 56;
        int r = tid - a_win * 56;
        int cg = r & 7, tg = r >> 3;
        a_t0 = tg * 8; a_c0 = cg * 8;
        const float* atp = s2 + a_win * PW + 800;
        const float* vp  = s2 + a_win * PW + 3544;
        #pragma unroll
        for (int p = 0; p < 4; p++)
            #pragma unroll
            for (int q = 0; q < 4; q++) { accA[p][q] = 0ull; accB[p][q] = 0ull; }
        #pragma unroll 2
        for (int m = 0; m < NTOK; m++) {
            const u64* ar = reinterpret_cast<const u64*>(atp + m * 56 + a_t0);
            const u64* vr = reinterpret_cast<const u64*>(vp  + m * 64 + a_c0);
            u64 av[4];
            #pragma unroll
            for (int p = 0; p < 4; p++) av[p] = ar[p];
            #pragma unroll
            for (int q = 0; q < 4; q++) {
                u64 vn = vr[q];
                u64 vs = f2swap(vn);
                #pragma unroll
                for (int p = 0; p < 4; p++) {
                    ffma2(accA[p][q], av[p], vn);
                    ffma2(accB[p][q], av[p], vs);
                }
            }
        }
    }
    __syncthreads();   // all att/v reads done before OS overlays pool

    if (tid < 224) {
        float* osp = s2 + a_win * PW;   // OS[t][c] stride 66
        #pragma unroll
        for (int p = 0; p < 4; p++) {
            int ta = a_t0 + 2 * p, tb = ta + 1;
            if (ta < NTOK) {
                #pragma unroll
                for (int q = 0; q < 4; q++)
                    *reinterpret_cast<float2*>(osp + ta * 66 + a_c0 + 2*q)
                        = make_float2(f2lo(accA[p][q]), f2lo(accB[p][q]));
            }
            if (tb < NTOK) {
                #pragma unroll
                for (int q = 0; q < 4; q++)
                    *reinterpret_cast<float2*>(osp + tb * 66 + a_c0 + 2*q)
                        = make_float2(f2hi(accB[p][q]), f2hi(accA[p][q]));
            }
        }
    }
    __syncthreads();

    // ---- residual + store: out = gamma*o + x (x reloaded from global) ----
    const float g = __ldg(gamma);
    const int h0 = wh * 7, w0 = wq * 28;
    const float* xb = x   + (size_t)b * CH * HWPIX;
    float*       ob = out + (size_t)b * CH * HWPIX;
    for (int idx = tid; idx < CH * 7 * 28; idx += 256) {
        int c  = idx / 196;
        int r  = idx - c * 196;
        int ph = r / 28;
        int pw = r - ph * 28;
        int win = pw / 7;
        int t   = ph * 7 + (pw - win * 7);
        float o_v = s2[win * PW + t * 66 + c];
        size_t gi = (size_t)c * HWPIX + (h0 + ph) * HWDIM + (w0 + pw);
        ob[gi] = fmaf(g, o_v, __ldg(&xb[gi]));
    }
}

extern "C" void kernel_launch(void* const* d_in, const int* in_sizes, int n_in,
                              void* d_out, int out_size)
{
    const float* x     = (const float*)d_in[0];
    const float* Wq    = (const float*)d_in[1];
    const float* bq    = (const float*)d_in[2];
    const float* Wk    = (const float*)d_in[3];
    const float* bk    = (const float*)d_in[4];
    const float* Wv    = (const float*)d_in[5];
    const float* bv    = (const float*)d_in[6];
    const float* gamma = (const float*)d_in[7];
    float* out = (float*)d_out;

    cudaFuncSetAttribute(proj_kernel, cudaFuncAttributeMaxDynamicSharedMemorySize, K1_SMEM_BYTES);
    cudaFuncSetAttribute(attn_kernel, cudaFuncAttributeMaxDynamicSharedMemorySize, K2_SMEM_BYTES);

    proj_kernel<<<NB * (HWPIX / 128), 128, K1_SMEM_BYTES>>>(x, Wq, bq, Wk, bk, Wv, bv);
    attn_kernel<<<NB * 32 * 8, 256, K2_SMEM_BYTES>>>(x, gamma, out);
}

// round 6
// speedup vs baseline: 1.4790x; 1.4790x over previous
#include <cuda_runtime.h>
#include <cstdint>

typedef unsigned long long u64;
typedef unsigned int u32;

#define HWDIM 224
#define HWPIX (HWDIM*HWDIM)   // 50176
#define NB    16
#define NTOK  49
#define CH    64
#define NOUT  80               // q(0..7) k(8..15) v(16..79)

// scratch: pixel-linear qkv [b][hw][80]
__device__ float g_qkv[(size_t)NB * HWPIX * NOUT];

__device__ __forceinline__ u64 f2swap(u64 v){
    u64 r;
    asm("{\n\t.reg .b32 l,h;\n\tmov.b64 {l,h}, %1;\n\tmov.b64 %0, {h,l};\n\t}"
        : "=l"(r) : "l"(v));
    return r;
}
__device__ __forceinline__ void ffma2(u64 &d, u64 a, u64 b){
    asm("fma.rn.f32x2 %0, %1, %2, %0;" : "+l"(d) : "l"(a), "l"(b));
}
__device__ __forceinline__ float f2lo(u64 v){ return __int_as_float((u32)(v & 0xffffffffull)); }
__device__ __forceinline__ float f2hi(u64 v){ return __int_as_float((u32)(v >> 32)); }

// ===================== K1: fused QKV projection =====================
// 128 threads, 128 pixels/block; tile 8px x 10 outs (diag f32x2).
// smem: xs[64][128]@0 (8192) | wct[64][80]@8192 (5120) | bias@13312 (80)
// epilogue: os1[128][80] overlays [0..10240)
#define K1_SMEM_FLOATS 13392
#define K1_SMEM_BYTES  (K1_SMEM_FLOATS*4)

__global__ void __launch_bounds__(128, 4)
proj_kernel(const float* __restrict__ x,
            const float* __restrict__ Wq, const float* __restrict__ bq,
            const float* __restrict__ Wk, const float* __restrict__ bk,
            const float* __restrict__ Wv, const float* __restrict__ bv)
{
    extern __shared__ float s1[];
    const int tid = threadIdx.x;
    const int blk = blockIdx.x;               // 16 * 392
    const int b   = blk / 392;
    const int hw0 = (blk - b * 392) * 128;

    // stage raw weights [o][c] stride 65 (in xs area, overwritten later)
    for (int idx = tid; idx < 512; idx += 128) {
        int o = idx >> 6, c = idx & 63;
        s1[o * 65 + c]       = __ldg(&Wq[idx]);
        s1[520 + o * 65 + c] = __ldg(&Wk[idx]);
    }
    for (int idx = tid; idx < 4096; idx += 128) {
        int o = idx >> 6, c = idx & 63;
        s1[1040 + o * 65 + c] = __ldg(&Wv[idx]);
    }
    if (tid < 80)
        s1[13312 + tid] = (tid < 8)  ? __ldg(&bq[tid])
                        : (tid < 16) ? __ldg(&bk[tid - 8])
                                     : __ldg(&bv[tid - 16]);
    __syncthreads();
    // transpose -> wct[c][80]: q(0..7) k(8..15) v(16..79)
    for (int idx = tid; idx < 5120; idx += 128) {
        int c = idx / 80, o = idx - c * 80;
        float v = (o < 8)  ? s1[o * 65 + c]
                : (o < 16) ? s1[520 + (o - 8) * 65 + c]
                           : s1[1040 + (o - 16) * 65 + c];
        s1[8192 + c * 80 + o] = v;
    }
    __syncthreads();
    // x tile -> xs[c][p] (overwrites raw stage)
    const float* xb = x + (size_t)b * CH * HWPIX + hw0;
    for (int idx = tid; idx < 8192; idx += 128) {
        int c = idx >> 7, p = idx & 127;
        s1[idx] = __ldg(&xb[(size_t)c * HWPIX + p]);
    }
    __syncthreads();

    // compute: tile 8px x 10 outs
    const int og = tid & 7, pg = tid >> 3;
    const int o0 = og * 10, p0 = pg * 8;

    u64 accA[4][5], accB[4][5];
    #pragma unroll
    for (int p = 0; p < 4; p++)
        #pragma unroll
        for (int q = 0; q < 5; q++) { accA[p][q] = 0ull; accB[p][q] = 0ull; }

    const u64* xbase = reinterpret_cast<const u64*>(s1) + (p0 >> 1);
    const u64* wbase = reinterpret_cast<const u64*>(s1 + 8192) + og * 5;

    #pragma unroll 2
    for (int c = 0; c < CH; c++) {
        u64 xv[4];
        #pragma unroll
        for (int p = 0; p < 4; p++) xv[p] = xbase[c * 64 + p];
        #pragma unroll
        for (int q = 0; q < 5; q++) {
            u64 wn = wbase[c * 40 + q];
            u64 ws = f2swap(wn);
            #pragma unroll
            for (int p = 0; p < 4; p++) {
                ffma2(accA[p][q], xv[p], wn);
                ffma2(accB[p][q], xv[p], ws);
            }
        }
    }
    __syncthreads();   // xs/wct reads done; os1 overlays them

    // epilogue stage: os1[p][80] @ s1[0..10240)
    const float* sb = s1 + 13312;
    #pragma unroll
    for (int p = 0; p < 4; p++) {
        int ta = p0 + 2 * p, tb = ta + 1;
        #pragma unroll
        for (int q = 0; q < 5; q++) {
            float b0 = sb[o0 + 2*q], b1 = sb[o0 + 2*q + 1];
            *reinterpret_cast<float2*>(s1 + ta * 80 + o0 + 2*q)
                = make_float2(f2lo(accA[p][q]) + b0, f2lo(accB[p][q]) + b1);
            *reinterpret_cast<float2*>(s1 + tb * 80 + o0 + 2*q)
                = make_float2(f2hi(accB[p][q]) + b0, f2hi(accA[p][q]) + b1);
        }
    }
    __syncthreads();

    // coalesced stream to g_qkv (128px * 80 floats contiguous)
    float4* dst = reinterpret_cast<float4*>(g_qkv + ((size_t)b * HWPIX + hw0) * NOUT);
    const float4* src = reinterpret_cast<const float4*>(s1);
    for (int i = tid; i < 2560; i += 128) dst[i] = src[i];
}

// ===================== K2: windowed attention =====================
// 128 threads, 2 horizontally-adjacent windows.
// pool/window (6768 floats): qkv[49][80]@0 (3920) | att[49][56]@3920 (2744+pad)
// os[49][66] (3234) overlays the qkv region (dead after AV compute).
#define PW 6768
#define OS_STRIDE 66
#define K2_SMEM_FLOATS (2*PW)          // 13536
#define K2_SMEM_BYTES  (K2_SMEM_FLOATS*4)   // 54144

__global__ void __launch_bounds__(128, 4)
attn_kernel(const float* __restrict__ x,
            const float* __restrict__ gamma,
            float* __restrict__ out)
{
    extern __shared__ float s2[];
    const int tid = threadIdx.x;
    const int blk = blockIdx.x;        // 16 b * 32 wh * 16 wpair
    const int b   = blk >> 9;
    const int rem = blk & 511;
    const int wh  = rem >> 4;
    const int wp  = rem & 15;
    const int h0  = wh * 7;
    const int w0  = wp * 14;

    const float g = __ldg(gamma);

    // ---- stage qkv: 7 rows of 14px*80 contiguous floats ----
    const float* gq = g_qkv + ((size_t)b * HWPIX + (size_t)h0 * HWDIM + w0) * NOUT;
    for (int i = tid; i < 1960; i += 128) {
        int ph = i / 280;
        int rr = i - ph * 280;
        int pw = rr / 20;
        int c4 = rr - pw * 20;
        int win = (pw >= 7);
        int t   = ph * 7 + pw - 7 * win;
        float4 v = __ldg(reinterpret_cast<const float4*>(gq + ((size_t)ph * HWDIM + pw) * NOUT) + c4);
        *reinterpret_cast<float4*>(s2 + win * PW + t * NOUT + c4 * 4) = v;
    }
    // zero att pad cols n = 49..55
    for (int i = tid; i < 686; i += 128) {
        int win = i / 343;
        int r   = i - win * 343;
        int m   = r / 7, j = r - m * 7;
        s2[win * PW + 3920 + m * 56 + 49 + j] = 0.0f;
    }
    __syncthreads();

    // ---- logits: attT[m][n] = <q_n, k_m>, 7x7 tiles ----
    if (tid < 98) {
        int win = tid / 49;
        int r   = tid - win * 49;
        int n0  = (r / 7) * 7, m0 = (r % 7) * 7;
        const float* pool = s2 + win * PW;
        float acc[7][7];
        #pragma unroll
        for (int i = 0; i < 7; i++)
            #pragma unroll
            for (int j = 0; j < 7; j++) acc[i][j] = 0.0f;
        #pragma unroll
        for (int c = 0; c < 8; c++) {
            float qv[7], kv[7];
            #pragma unroll
            for (int i = 0; i < 7; i++) qv[i] = pool[(n0 + i) * NOUT + c];
            #pragma unroll
            for (int j = 0; j < 7; j++) kv[j] = pool[(m0 + j) * NOUT + 8 + c];
            #pragma unroll
            for (int i = 0; i < 7; i++)
                #pragma unroll
                for (int j = 0; j < 7; j++) acc[i][j] = fmaf(qv[i], kv[j], acc[i][j]);
        }
        float* atp = s2 + win * PW + 3920;
        #pragma unroll
        for (int i = 0; i < 7; i++)
            #pragma unroll
            for (int j = 0; j < 7; j++)
                atp[(m0 + j) * 56 + (n0 + i)] = acc[i][j];
    }
    __syncthreads();

    // ---- softmax over keys m (columns), gamma folded into normalization ----
    if (tid < 98) {
        int win = tid / 49;
        int n   = tid - win * 49;
        float* atp = s2 + win * PW + 3920 + n;
        float mx = atp[0];
        #pragma unroll 7
        for (int m = 1; m < NTOK; m++) mx = fmaxf(mx, atp[m * 56]);
        float s = 0.0f;
        #pragma unroll 7
        for (int m = 0; m < NTOK; m++) {
            float e = __expf(atp[m * 56] - mx);
            atp[m * 56] = e;
            s += e;
        }
        float rs = g / s;
        #pragma unroll 7
        for (int m = 0; m < NTOK; m++) atp[m * 56] *= rs;
    }
    __syncthreads();

    // ---- AV: out[n][c] = sum_m att[m][n]*v[m][c], tile 8t x 8c ----
    u64 accA[4][4], accB[4][4];
    int a_win = 0, a_t0 = 0, a_c0 = 0;
    if (tid < 112) {
        a_win = tid / 56;
        int r = tid - a_win * 56;
        int cg = r & 7, tg = r >> 3;
        a_t0 = tg * 8; a_c0 = cg * 8;
        const float* atb = s2 + a_win * PW + 3920 + a_t0;
        const float* vb  = s2 + a_win * PW + 16 + a_c0;
        #pragma unroll
        for (int p = 0; p < 4; p++)
            #pragma unroll
            for (int q = 0; q < 4; q++) { accA[p][q] = 0ull; accB[p][q] = 0ull; }
        #pragma unroll 2
        for (int m = 0; m < NTOK; m++) {
            const u64* ar = reinterpret_cast<const u64*>(atb + m * 56);
            const u64* vr = reinterpret_cast<const u64*>(vb + m * NOUT);
            u64 av[4];
            #pragma unroll
            for (int p = 0; p < 4; p++) av[p] = ar[p];
            #pragma unroll
            for (int q = 0; q < 4; q++) {
                u64 vn = vr[q];
                u64 vs = f2swap(vn);
                #pragma unroll
                for (int p = 0; p < 4; p++) {
                    ffma2(accA[p][q], av[p], vn);
                    ffma2(accB[p][q], av[p], vs);
                }
            }
        }
    }
    __syncthreads();   // all att/v reads done before os overlays the qkv region

    if (tid < 112) {
        float* osp = s2 + a_win * PW;   // os[t][c] stride 66 (over dead qkv)
        #pragma unroll
        for (int p = 0; p < 4; p++) {
            int ta = a_t0 + 2 * p, tb = ta + 1;
            if (ta < NTOK) {
                #pragma unroll
                for (int q = 0; q < 4; q++)
                    *reinterpret_cast<float2*>(osp + ta * OS_STRIDE + a_c0 + 2*q)
                        = make_float2(f2lo(accA[p][q]), f2lo(accB[p][q]));
            }
            if (tb < NTOK) {
                #pragma unroll
                for (int q = 0; q < 4; q++)
                    *reinterpret_cast<float2*>(osp + tb * OS_STRIDE + a_c0 + 2*q)
                        = make_float2(f2hi(accB[p][q]), f2hi(accA[p][q]));
            }
        }
    }
    __syncthreads();

    // ---- residual + store: out = os + x (gamma already applied) ----
    if (tid < 112) {
        int ph = tid >> 4, pw = tid & 15;
        if (pw < 14) {
            int win = (pw >= 7);
            int t   = ph * 7 + pw - 7 * win;
            const float* osr = s2 + win * PW + t * OS_STRIDE;
            size_t gi = (size_t)b * CH * HWPIX + (size_t)(h0 + ph) * HWDIM + (w0 + pw);
            #pragma unroll 4
            for (int c = 0; c < CH; c++) {
                out[gi] = osr[c] + __ldg(&x[gi]);
                gi += HWPIX;
            }
        }
    }
}

extern "C" void kernel_launch(void* const* d_in, const int* in_sizes, int n_in,
                              void* d_out, int out_size)
{
    const float* x     = (const float*)d_in[0];
    const float* Wq    = (const float*)d_in[1];
    const float* bq    = (const float*)d_in[2];
    const float* Wk    = (const float*)d_in[3];
    const float* bk    = (const float*)d_in[4];
    const float* Wv    = (const float*)d_in[5];
    const float* bv    = (const float*)d_in[6];
    const float* gamma = (const float*)d_in[7];
    float* out = (float*)d_out;

    cudaFuncSetAttribute(proj_kernel, cudaFuncAttributeMaxDynamicSharedMemorySize, K1_SMEM_BYTES);
    cudaFuncSetAttribute(attn_kernel, cudaFuncAttributeMaxDynamicSharedMemorySize, K2_SMEM_BYTES);

    proj_kernel<<<NB * (HWPIX / 128), 128, K1_SMEM_BYTES>>>(x, Wq, bq, Wk, bk, Wv, bv);
    attn_kernel<<<NB * 32 * 16, 128, K2_SMEM_BYTES>>>(x, gamma, out);
}